// round 3
// baseline (speedup 1.0000x reference)
#include <cuda_runtime.h>

#define NNZ        400000
#define NUM_EDGES  20000
#define NUM_NODES  40000   // B*N = 4*10000
#define FDIM       64
#define TDIM       4
#define ROW        256     // FDIM*TDIM floats per node/edge feature row

// ---------------- scratch (device globals; no runtime allocation) ----------
__device__ __align__(16) float g_xw[NUM_NODES * ROW];          // [node][t*64+o]
__device__ __align__(16) float g_edge_feat[NUM_EDGES * ROW];   // [edge][t*64+o]
__device__ float g_D[NUM_NODES];

__device__ int g_is64;                           // 1 if HE delivered as int64
__device__ int g_edge_cnt[NUM_EDGES];
__device__ int g_edge_start[NUM_EDGES + 1];
__device__ int g_edge_pos[NUM_EDGES];
__device__ int g_node_cnt[NUM_NODES];
__device__ int g_node_start[NUM_NODES + 1];
__device__ int g_node_pos[NUM_NODES];
__device__ int g_edge_items[NNZ];                // node indices bucketed by edge
__device__ int g_node_items[NNZ];                // edge indices bucketed by node

// Decode incidence pair i from HE viewed as int32 words.
__device__ __forceinline__ void load_pair(const int* __restrict__ he32, int i,
                                          int is64, int& n, int& e) {
    if (is64) {
        n = he32[2 * i];                 // low word of int64
        e = he32[2 * (NNZ + i)];
    } else {
        n = he32[i];
        e = he32[NNZ + i];
    }
}

// ---------------- K1: zero counters / degrees + dtype probe -----------------
__global__ void zero_kernel(const int* __restrict__ he32) {
    int i = blockIdx.x * blockDim.x + threadIdx.x;
    if (i == 0) {
        // int64 little-endian with values < 2^31 => all odd words of row 0 are 0
        int orv = 0;
        #pragma unroll 8
        for (int k = 0; k < 64; k++) orv |= he32[2 * k + 1];
        g_is64 = (orv == 0) ? 1 : 0;
    }
    if (i < NUM_NODES) { g_D[i] = 0.0f; g_node_cnt[i] = 0; g_node_pos[i] = 0; }
    if (i < NUM_EDGES) { g_edge_cnt[i] = 0; g_edge_pos[i] = 0; }
}

// ---------------- K2: histogram + weighted node degree ----------------------
__global__ void count_kernel(const int* __restrict__ he32,
                             const float* __restrict__ HEWI) {
    int i = blockIdx.x * blockDim.x + threadIdx.x;
    if (i >= NNZ) return;
    int n, e;
    load_pair(he32, i, g_is64, n, e);
    if ((unsigned)n >= NUM_NODES || (unsigned)e >= NUM_EDGES) return;
    atomicAdd(&g_edge_cnt[e], 1);
    atomicAdd(&g_node_cnt[n], 1);
    atomicAdd(&g_D[n], HEWI[e]);
}

// ---------------- K3: single-block exclusive scan (shfl-based) --------------
// which==0 -> edges, which==1 -> nodes
__global__ void scan_kernel(int which) {
    const int* cnt = (which == 0) ? g_edge_cnt : g_node_cnt;
    int* out       = (which == 0) ? g_edge_start : g_node_start;
    int n          = (which == 0) ? NUM_EDGES : NUM_NODES;

    __shared__ int warp_tot[32];
    __shared__ int s_carry;
    int lane = threadIdx.x & 31;
    int wid  = threadIdx.x >> 5;
    if (threadIdx.x == 0) s_carry = 0;
    __syncthreads();

    for (int base = 0; base < n; base += 1024) {
        int i = base + threadIdx.x;
        int orig = (i < n) ? cnt[i] : 0;
        int v = orig;
        #pragma unroll
        for (int off = 1; off < 32; off <<= 1) {
            int t = __shfl_up_sync(0xffffffffu, v, off);
            if (lane >= off) v += t;
        }
        if (lane == 31) warp_tot[wid] = v;
        __syncthreads();
        if (wid == 0) {
            int wv = warp_tot[lane];
            #pragma unroll
            for (int off = 1; off < 32; off <<= 1) {
                int t = __shfl_up_sync(0xffffffffu, wv, off);
                if (lane >= off) wv += t;
            }
            warp_tot[lane] = wv;
        }
        __syncthreads();
        int prefix = s_carry + ((wid > 0) ? warp_tot[wid - 1] : 0);
        if (i < n) out[i] = prefix + v - orig;   // exclusive
        __syncthreads();
        if (threadIdx.x == 0) s_carry += warp_tot[31];
        __syncthreads();
    }
    if (threadIdx.x == 0) out[n] = s_carry;
}

// ---------------- K4: fill CSR buckets --------------------------------------
__global__ void fill_kernel(const int* __restrict__ he32) {
    int i = blockIdx.x * blockDim.x + threadIdx.x;
    if (i >= NNZ) return;
    int n, e;
    load_pair(he32, i, g_is64, n, e);
    if ((unsigned)n >= NUM_NODES || (unsigned)e >= NUM_EDGES) return;
    int pe = atomicAdd(&g_edge_pos[e], 1);
    g_edge_items[g_edge_start[e] + pe] = n;
    int pn = atomicAdd(&g_node_pos[n], 1);
    g_node_items[g_node_start[n] + pn] = e;
}

// ---------------- K5: per-node linear xw = x @ W ----------------------------
// x layout: [node][f*4+t] (256 contiguous floats per node)
// out layout: [node][t*64+o]
#define NPB 16
__global__ void xw_kernel(const float* __restrict__ x,
                          const float* __restrict__ W) {
    __shared__ float Ws[FDIM * FDIM];   // 16 KB
    __shared__ float xs[NPB * ROW];     // 16 KB
    int tid = threadIdx.x;              // 256 threads
    int base = blockIdx.x * NPB;

    for (int i = tid; i < FDIM * FDIM; i += 256) Ws[i] = W[i];
    for (int i = tid; i < NPB * ROW; i += 256)   xs[i] = x[base * ROW + i];
    __syncthreads();

    int t = tid >> 6;      // 0..3
    int o = tid & 63;      // 0..63
    for (int j = 0; j < NPB; j++) {
        float acc = 0.0f;
        #pragma unroll
        for (int f = 0; f < FDIM; f++)
            acc += xs[j * ROW + f * 4 + t] * Ws[f * 64 + o];
        g_xw[(base + j) * ROW + tid] = acc;   // tid == t*64+o
    }
}

// ---------------- K6: edge aggregation (gather, no atomics) -----------------
// edge_feat[e] = B_inv[e] * sum_{v in e} xw[v]
__global__ void edge_agg_kernel() {
    int e = blockIdx.x;
    int tid = threadIdx.x;   // 64 threads; thread owns float4 at tid*4
    int s  = g_edge_start[e];
    int en = g_edge_start[e + 1];
    float4 acc = make_float4(0.f, 0.f, 0.f, 0.f);
    for (int i = s; i < en; i++) {
        int nd = g_edge_items[i];
        float4 v = *(const float4*)(g_xw + (size_t)nd * ROW + tid * 4);
        acc.x += v.x; acc.y += v.y; acc.z += v.z; acc.w += v.w;
    }
    float binv = (en > s) ? 1.0f / (float)(en - s) : 0.0f;
    acc.x *= binv; acc.y *= binv; acc.z *= binv; acc.w *= binv;
    *(float4*)(g_edge_feat + (size_t)e * ROW + tid * 4) = acc;
}

// ---------------- K7: node aggregation + D_inv + bias + ReLU + transpose ----
// out[n][o*4+t] = relu( D_inv[n] * sum_{e ni n} edge_feat[e][t*64+o] + b[o] )
__global__ void node_agg_kernel(const float* __restrict__ b,
                                float* __restrict__ out) {
    int n = blockIdx.x;
    int o = threadIdx.x;     // 64 threads; thread owns output float4 at o*4
    int s  = g_node_start[n];
    int en = g_node_start[n + 1];
    float a0 = 0.f, a1 = 0.f, a2 = 0.f, a3 = 0.f;
    for (int i = s; i < en; i++) {
        int e = g_node_items[i];
        const float* ef = g_edge_feat + (size_t)e * ROW;
        a0 += ef[0 * 64 + o];
        a1 += ef[1 * 64 + o];
        a2 += ef[2 * 64 + o];
        a3 += ef[3 * 64 + o];
    }
    float Dv = g_D[n];
    float dinv = (Dv > 0.f) ? 1.0f / Dv : 0.0f;
    float bo = b[o];
    float4 r;
    r.x = fmaxf(a0 * dinv + bo, 0.0f);
    r.y = fmaxf(a1 * dinv + bo, 0.0f);
    r.z = fmaxf(a2 * dinv + bo, 0.0f);
    r.w = fmaxf(a3 * dinv + bo, 0.0f);
    *(float4*)(out + (size_t)n * ROW + o * 4) = r;
}

// ---------------- launch -----------------------------------------------------
extern "C" void kernel_launch(void* const* d_in, const int* in_sizes, int n_in,
                              void* d_out, int out_size) {
    const float* x    = (const float*)d_in[0];      // [4,10000,64,4]
    const int*   he32 = (const int*)d_in[1];        // [2, 400000] (int32 or int64 words)
    const float* HEWI = (const float*)d_in[2];      // [20000]
    const float* W    = (const float*)d_in[3];      // [64,64]
    const float* b    = (const float*)d_in[4];      // [64]
    float* out = (float*)d_out;                     // [4,10000,64,4]

    zero_kernel<<<(NUM_NODES + 255) / 256, 256>>>(he32);
    count_kernel<<<(NNZ + 255) / 256, 256>>>(he32, HEWI);
    scan_kernel<<<1, 1024>>>(0);   // edges
    scan_kernel<<<1, 1024>>>(1);   // nodes
    fill_kernel<<<(NNZ + 255) / 256, 256>>>(he32);
    xw_kernel<<<NUM_NODES / NPB, 256>>>(x, W);
    edge_agg_kernel<<<NUM_EDGES, 64>>>();
    node_agg_kernel<<<NUM_NODES, 64>>>(b, out);
}

// round 4
// speedup vs baseline: 1.1750x; 1.1750x over previous
#include <cuda_runtime.h>

#define NNZ        400000
#define NUM_EDGES  20000
#define NUM_NODES  40000   // B*N = 4*10000
#define FDIM       64
#define TDIM       4
#define ROW        256     // FDIM*TDIM floats per node/edge feature row

// ---------------- scratch (device globals; no runtime allocation) ----------
__device__ __align__(16) float g_xw[NUM_NODES * ROW];          // [node][t*64+o]
__device__ __align__(16) float g_edge_feat[NUM_EDGES * ROW];   // [edge][t*64+o]
__device__ float g_D[NUM_NODES];

__device__ int g_is64;                           // 1 if HE delivered as int64
__device__ int g_cursor_e;                       // bucket cursors (unordered CSR)
__device__ int g_cursor_n;
__device__ int g_edge_cnt[NUM_EDGES];
__device__ int g_edge_start[NUM_EDGES];
__device__ int g_edge_pos[NUM_EDGES];
__device__ int g_node_cnt[NUM_NODES];
__device__ int g_node_start[NUM_NODES];
__device__ int g_node_pos[NUM_NODES];
__device__ int g_edge_items[NNZ];                // node indices bucketed by edge
__device__ int g_node_items[NNZ];                // edge indices bucketed by node

// Decode incidence pair i from HE viewed as int32 words.
__device__ __forceinline__ void load_pair(const int* __restrict__ he32, int i,
                                          int is64, int& n, int& e) {
    if (is64) {
        n = he32[2 * i];                 // low word of int64
        e = he32[2 * (NNZ + i)];
    } else {
        n = he32[i];
        e = he32[NNZ + i];
    }
}

// ---------------- K1: zero counters / degrees + dtype probe -----------------
__global__ void zero_kernel(const int* __restrict__ he32) {
    int i = blockIdx.x * blockDim.x + threadIdx.x;
    if (i == 0) {
        // int64 little-endian with values < 2^31 => all odd words of row 0 are 0
        int orv = 0;
        #pragma unroll 8
        for (int k = 0; k < 64; k++) orv |= he32[2 * k + 1];
        g_is64 = (orv == 0) ? 1 : 0;
        g_cursor_e = 0;
        g_cursor_n = 0;
    }
    if (i < NUM_NODES) { g_D[i] = 0.0f; g_node_cnt[i] = 0; g_node_pos[i] = 0; }
    if (i < NUM_EDGES) { g_edge_cnt[i] = 0; g_edge_pos[i] = 0; }
}

// ---------------- K2: histogram + weighted node degree ----------------------
__global__ void count_kernel(const int* __restrict__ he32,
                             const float* __restrict__ HEWI) {
    int i = blockIdx.x * blockDim.x + threadIdx.x;
    if (i >= NNZ) return;
    int n, e;
    load_pair(he32, i, g_is64, n, e);
    if ((unsigned)n >= NUM_NODES || (unsigned)e >= NUM_EDGES) return;
    atomicAdd(&g_edge_cnt[e], 1);
    atomicAdd(&g_node_cnt[n], 1);
    atomicAdd(&g_D[n], HEWI[e]);
}

// ---------------- K3: unordered CSR offsets via warp-aggregated cursor ------
// Order of buckets is irrelevant: start is stored explicitly, end = start+cnt.
__device__ __forceinline__ void assign_offsets(const int* __restrict__ cnt,
                                               int* __restrict__ start,
                                               int* __restrict__ cursor,
                                               int n, int i, int lane) {
    int c = (i < n) ? cnt[i] : 0;
    int p = c;
    #pragma unroll
    for (int off = 1; off < 32; off <<= 1) {
        int t = __shfl_up_sync(0xffffffffu, p, off);
        if (lane >= off) p += t;
    }
    int excl = p - c;
    int tot = __shfl_sync(0xffffffffu, p, 31);
    int base = 0;
    if (lane == 0 && tot > 0) base = atomicAdd(cursor, tot);
    base = __shfl_sync(0xffffffffu, base, 0);
    if (i < n) start[i] = base + excl;
}

__global__ void offsets_kernel() {
    int i = blockIdx.x * blockDim.x + threadIdx.x;
    int lane = threadIdx.x & 31;
    assign_offsets(g_edge_cnt, g_edge_start, &g_cursor_e, NUM_EDGES, i, lane);
    assign_offsets(g_node_cnt, g_node_start, &g_cursor_n, NUM_NODES, i, lane);
}

// ---------------- K4: fill CSR buckets --------------------------------------
__global__ void fill_kernel(const int* __restrict__ he32) {
    int i = blockIdx.x * blockDim.x + threadIdx.x;
    if (i >= NNZ) return;
    int n, e;
    load_pair(he32, i, g_is64, n, e);
    if ((unsigned)n >= NUM_NODES || (unsigned)e >= NUM_EDGES) return;
    int pe = atomicAdd(&g_edge_pos[e], 1);
    g_edge_items[g_edge_start[e] + pe] = n;
    int pn = atomicAdd(&g_node_pos[n], 1);
    g_node_items[g_node_start[n] + pn] = e;
}

// ---------------- K5: per-node linear xw = x @ W ----------------------------
// x layout: [node][f*4+t] (256 contiguous floats per node)
// out layout: [node][t*64+o]
#define NPB 16
__global__ void xw_kernel(const float* __restrict__ x,
                          const float* __restrict__ W) {
    __shared__ float Ws[FDIM * FDIM];   // 16 KB
    __shared__ float xs[NPB * ROW];     // 16 KB
    int tid = threadIdx.x;              // 256 threads
    int base = blockIdx.x * NPB;

    for (int i = tid; i < FDIM * FDIM; i += 256) Ws[i] = W[i];
    for (int i = tid; i < NPB * ROW; i += 256)   xs[i] = x[base * ROW + i];
    __syncthreads();

    int t = tid >> 6;      // 0..3
    int o = tid & 63;      // 0..63
    for (int j = 0; j < NPB; j++) {
        float acc = 0.0f;
        #pragma unroll
        for (int f = 0; f < FDIM; f++)
            acc += xs[j * ROW + f * 4 + t] * Ws[f * 64 + o];
        g_xw[(base + j) * ROW + tid] = acc;   // tid == t*64+o
    }
}

// ---------------- K6: edge aggregation (gather, no atomics) -----------------
// edge_feat[e] = B_inv[e] * sum_{v in e} xw[v]
__global__ void edge_agg_kernel() {
    int e = blockIdx.x;
    int tid = threadIdx.x;   // 64 threads; thread owns float4 at tid*4
    int s   = g_edge_start[e];
    int cnt = g_edge_cnt[e];
    int en  = s + cnt;
    float4 acc = make_float4(0.f, 0.f, 0.f, 0.f);
    for (int i = s; i < en; i++) {
        int nd = g_edge_items[i];
        float4 v = *(const float4*)(g_xw + (size_t)nd * ROW + tid * 4);
        acc.x += v.x; acc.y += v.y; acc.z += v.z; acc.w += v.w;
    }
    float binv = (cnt > 0) ? 1.0f / (float)cnt : 0.0f;
    acc.x *= binv; acc.y *= binv; acc.z *= binv; acc.w *= binv;
    *(float4*)(g_edge_feat + (size_t)e * ROW + tid * 4) = acc;
}

// ---------------- K7: node aggregation + D_inv + bias + ReLU + transpose ----
// out[n][o*4+t] = relu( D_inv[n] * sum_{e ni n} edge_feat[e][t*64+o] + b[o] )
__global__ void node_agg_kernel(const float* __restrict__ b,
                                float* __restrict__ out) {
    int n = blockIdx.x;
    int o = threadIdx.x;     // 64 threads; thread owns output float4 at o*4
    int s  = g_node_start[n];
    int en = s + g_node_cnt[n];
    float a0 = 0.f, a1 = 0.f, a2 = 0.f, a3 = 0.f;
    for (int i = s; i < en; i++) {
        int e = g_node_items[i];
        const float* ef = g_edge_feat + (size_t)e * ROW;
        a0 += ef[0 * 64 + o];
        a1 += ef[1 * 64 + o];
        a2 += ef[2 * 64 + o];
        a3 += ef[3 * 64 + o];
    }
    float Dv = g_D[n];
    float dinv = (Dv > 0.f) ? 1.0f / Dv : 0.0f;
    float bo = b[o];
    float4 r;
    r.x = fmaxf(a0 * dinv + bo, 0.0f);
    r.y = fmaxf(a1 * dinv + bo, 0.0f);
    r.z = fmaxf(a2 * dinv + bo, 0.0f);
    r.w = fmaxf(a3 * dinv + bo, 0.0f);
    *(float4*)(out + (size_t)n * ROW + o * 4) = r;
}

// ---------------- launch -----------------------------------------------------
extern "C" void kernel_launch(void* const* d_in, const int* in_sizes, int n_in,
                              void* d_out, int out_size) {
    const float* x    = (const float*)d_in[0];      // [4,10000,64,4]
    const int*   he32 = (const int*)d_in[1];        // [2, 400000] (int32 or int64 words)
    const float* HEWI = (const float*)d_in[2];      // [20000]
    const float* W    = (const float*)d_in[3];      // [64,64]
    const float* b    = (const float*)d_in[4];      // [64]
    float* out = (float*)d_out;                     // [4,10000,64,4]

    zero_kernel<<<(NUM_NODES + 255) / 256, 256>>>(he32);
    count_kernel<<<(NNZ + 255) / 256, 256>>>(he32, HEWI);
    offsets_kernel<<<(NUM_NODES + 255) / 256, 256>>>();
    fill_kernel<<<(NNZ + 255) / 256, 256>>>(he32);
    xw_kernel<<<NUM_NODES / NPB, 256>>>(x, W);
    edge_agg_kernel<<<NUM_EDGES, 64>>>();
    node_agg_kernel<<<NUM_NODES, 64>>>(b, out);
}